// round 13
// baseline (speedup 1.0000x reference)
#include <cuda_runtime.h>
#include <cstdint>

#define NHID 64
#define EXTD 32
#define MAXN 50000
#define TILE_E 128

// K' = 288 (3 terms x 96). Row stride 328 bf16 = 656 B (=> +4 banks/row: ldmatrix conflict-free)
#define KP 288
#define ROW_STRIDE_BF16 328
#define ROW_STRIDE_B 656
#define A_BYTES (128 * ROW_STRIDE_B)        // 83968
#define B_BYTES (64 * ROW_STRIDE_B)         // 41984
#define SO_ROW_B 272                        // 34 float2 per row
#define SO_BYTES (128 * SO_ROW_B)           // 34816
#define SMEM_A 0
#define SMEM_BW (A_BYTES)                   // 83968
#define SMEM_SO (A_BYTES + B_BYTES)         // 125952
#define SMEM_TOTAL (SMEM_SO + SO_BYTES)     // 160768

// Device scratch
__device__ __align__(16) float g_M[192 * 64];
__device__ __align__(16) float g_c[64];
__device__ __align__(16) float g_Pa[MAXN * 64];
__device__ __align__(16) float g_Pc[MAXN * 64];
__device__ __align__(16) unsigned short g_Bf[64 * ROW_STRIDE_BF16];  // B' bf16 [n][k']

// ---------------- helpers ----------------
__device__ __forceinline__ uint32_t smem_u32(const void* p) {
    uint32_t a;
    asm("{ .reg .u64 t; cvta.to.shared.u64 t, %1; cvt.u32.u64 %0, t; }" : "=r"(a) : "l"(p));
    return a;
}
__device__ __forceinline__ uint32_t cvt_bf16x2(float hi, float lo) {
    uint32_t d;
    asm("cvt.rn.satfinite.bf16x2.f32 %0, %1, %2;" : "=r"(d) : "f"(hi), "f"(lo));
    return d;
}
__device__ __forceinline__ void ldsm_x4(uint32_t& r0, uint32_t& r1, uint32_t& r2, uint32_t& r3,
                                        uint32_t addr) {
    asm volatile("ldmatrix.sync.aligned.m8n8.x4.shared.b16 {%0,%1,%2,%3}, [%4];"
                 : "=r"(r0), "=r"(r1), "=r"(r2), "=r"(r3) : "r"(addr));
}
__device__ __forceinline__ void mma_bf16(float* d, uint32_t a0, uint32_t a1, uint32_t a2,
                                         uint32_t a3, uint32_t b0, uint32_t b1) {
    asm volatile("mma.sync.aligned.m16n8k16.row.col.f32.bf16.bf16.f32 "
                 "{%0,%1,%2,%3}, {%4,%5,%6,%7}, {%8,%9}, {%0,%1,%2,%3};"
                 : "+f"(d[0]), "+f"(d[1]), "+f"(d[2]), "+f"(d[3])
                 : "r"(a0), "r"(a1), "r"(a2), "r"(a3), "r"(b0), "r"(b1));
}

// ---------------------------------------------------------------------------
// Kernel 0: compose M = W1 @ W2a (192x64), c = b1 @ W2a + b2.
// ---------------------------------------------------------------------------
__global__ __launch_bounds__(256) void compose_kernel(const float* __restrict__ W1,
                                                      const float* __restrict__ b1,
                                                      const float* __restrict__ W2,
                                                      const float* __restrict__ b2) {
    int idx = blockIdx.x * blockDim.x + threadIdx.x;
    if (idx < 12288) {
        int r = idx >> 6, j = idx & 63;
        float s = 0.f;
#pragma unroll 16
        for (int k = 0; k < 64; ++k) s += W1[r * 64 + k] * W2[k * 64 + j];
        g_M[idx] = s;
    } else if (idx < 12352) {
        int j = idx - 12288;
        float s = b2[j];
#pragma unroll 16
        for (int k = 0; k < 64; ++k) s += b1[k] * W2[k * 64 + j];
        g_c[j] = s;
    }
}

// ---------------------------------------------------------------------------
// Kernel 0b: build bf16 B' [64][328]: k'=[0,96) bhi, [96,192) bhi, [192,288) blo, pad 0.
// B[k][n] = k<64 ? g_M[(64+k)*64+n] : W2[k*64+n].
// ---------------------------------------------------------------------------
__global__ __launch_bounds__(256) void bprep_kernel(const float* __restrict__ W2) {
    int idx = blockIdx.x * blockDim.x + threadIdx.x;
    if (idx >= 64 * ROW_STRIDE_BF16) return;
    int n = idx / ROW_STRIDE_BF16;
    int kp = idx - n * ROW_STRIDE_BF16;
    unsigned short val = 0;
    if (kp < KP) {
        int k = kp % 96;
        float b = (k < 64) ? g_M[(64 + k) * 64 + n] : W2[k * 64 + n];
        unsigned short hi = (unsigned short)(cvt_bf16x2(0.f, b) & 0xffffu);
        if (kp < 192) {
            val = hi;
        } else {
            float hf = __uint_as_float(((uint32_t)hi) << 16);
            val = (unsigned short)(cvt_bf16x2(0.f, b - hf) & 0xffffu);
        }
    }
    g_Bf[idx] = val;
}

// ---------------------------------------------------------------------------
// Kernel 1: node projections Pa = h @ Ma, Pc = h @ Mc. Warp per node.
// ---------------------------------------------------------------------------
__global__ __launch_bounds__(256) void nodeproj_kernel(const float* __restrict__ h,
                                                       int nNodes) {
    __shared__ float sMa[64 * 64];
    __shared__ float sMc[64 * 64];
    int tid = threadIdx.x;
    for (int i = tid; i < 64 * 64; i += blockDim.x) {
        sMa[i] = g_M[i];
        sMc[i] = g_M[128 * 64 + i];
    }
    __syncthreads();

    int warp = tid >> 5, lane = tid & 31;
    int n = blockIdx.x * 8 + warp;
    if (n >= nNodes || n >= MAXN) return;

    float h0 = h[n * 64 + lane];
    float h1 = h[n * 64 + 32 + lane];
    float a0 = 0.f, a1 = 0.f, c0 = 0.f, c1 = 0.f;
#pragma unroll
    for (int k = 0; k < 64; ++k) {
        float hk = __shfl_sync(0xffffffffu, (k < 32) ? h0 : h1, k & 31);
        a0 += hk * sMa[k * 64 + lane];
        a1 += hk * sMa[k * 64 + 32 + lane];
        c0 += hk * sMc[k * 64 + lane];
        c1 += hk * sMc[k * 64 + 32 + lane];
    }
    g_Pa[n * 64 + lane] = a0;
    g_Pa[n * 64 + 32 + lane] = a1;
    g_Pc[n * 64 + lane] = c0;
    g_Pc[n * 64 + 32 + lane] = c1;
}

// ---------------------------------------------------------------------------
// Kernel 2: edge GEMM via bf16 mma.sync (HMMA). One 128-edge tile per block.
// ---------------------------------------------------------------------------
__global__ __launch_bounds__(256) void edge_kernel(const float* __restrict__ e_h,
                                                   const float* __restrict__ ext,
                                                   const int* __restrict__ src,
                                                   const int* __restrict__ dst,
                                                   float* __restrict__ out,
                                                   int E) {
    extern __shared__ __align__(16) char smem[];
    char* sA = smem + SMEM_A;
    char* sB = smem + SMEM_BW;
    uint32_t sb = smem_u32(smem);

    int tid = threadIdx.x;
    int warp = tid >> 5;
    int lane = tid & 31;
    long base = (long)blockIdx.x * TILE_E;

    // ---- Phase 1: convert A tile (fp32 -> 3-term bf16 split) + copy B'
#pragma unroll
    for (int it = 0; it < 8; ++it) {          // e_h: 128 x 64 = 2048 float4
        int p = tid + it * 256;
        int e = p >> 4;
        int k0 = (p & 15) << 2;
        long ge = base + e;
        float4 x = make_float4(0.f, 0.f, 0.f, 0.f);
        if (ge < E) x = *(const float4*)&e_h[ge * 64 + k0];
        uint32_t hi01 = cvt_bf16x2(x.y, x.x);
        uint32_t hi23 = cvt_bf16x2(x.w, x.z);
        float r0 = x.x - __uint_as_float(hi01 << 16);
        float r1 = x.y - __uint_as_float(hi01 & 0xffff0000u);
        float r2 = x.z - __uint_as_float(hi23 << 16);
        float r3 = x.w - __uint_as_float(hi23 & 0xffff0000u);
        uint32_t lo01 = cvt_bf16x2(r1, r0);
        uint32_t lo23 = cvt_bf16x2(r3, r2);
        char* row = sA + e * ROW_STRIDE_B;
        *(uint2*)(row + k0 * 2) = make_uint2(hi01, hi23);
        *(uint2*)(row + (k0 + 96) * 2) = make_uint2(lo01, lo23);
        *(uint2*)(row + (k0 + 192) * 2) = make_uint2(hi01, hi23);
    }
#pragma unroll
    for (int it = 0; it < 4; ++it) {          // ext: 128 x 32 = 1024 float4
        int p = tid + it * 256;
        int e = p >> 3;
        int k0 = 64 + ((p & 7) << 2);
        long ge = base + e;
        float4 x = make_float4(0.f, 0.f, 0.f, 0.f);
        if (ge < E) x = *(const float4*)&ext[ge * 32 + (k0 - 64)];
        uint32_t hi01 = cvt_bf16x2(x.y, x.x);
        uint32_t hi23 = cvt_bf16x2(x.w, x.z);
        float r0 = x.x - __uint_as_float(hi01 << 16);
        float r1 = x.y - __uint_as_float(hi01 & 0xffff0000u);
        float r2 = x.z - __uint_as_float(hi23 << 16);
        float r3 = x.w - __uint_as_float(hi23 & 0xffff0000u);
        uint32_t lo01 = cvt_bf16x2(r1, r0);
        uint32_t lo23 = cvt_bf16x2(r3, r2);
        char* row = sA + e * ROW_STRIDE_B;
        *(uint2*)(row + k0 * 2) = make_uint2(hi01, hi23);
        *(uint2*)(row + (k0 + 96) * 2) = make_uint2(lo01, lo23);
        *(uint2*)(row + (k0 + 192) * 2) = make_uint2(hi01, hi23);
    }
    // B' copy: 41984 B = 2624 float4
#pragma unroll
    for (int it = 0; it < 11; ++it) {
        int p = tid + it * 256;
        if (p < 2624) *(float4*)(sB + p * 16) = *(const float4*)((const char*)g_Bf + p * 16);
    }
    __syncthreads();

    // ---- Phase 2: HMMA mainloop. Warp: 16 edges x 64 cols; 18 k16-steps.
    // A fragment addresses: row = warp*16 + (lane&15), col-half by lane bit4.
    uint32_t aAddr = sb + SMEM_A + (warp * 16 + (lane & 15)) * ROW_STRIDE_B
                     + ((lane & 16) ? 16 : 0);
    uint32_t bAddr[4];
#pragma unroll
    for (int p = 0; p < 4; ++p) {
        int n = p * 16 + (lane & 7) + ((lane & 16) ? 8 : 0);
        bAddr[p] = sb + SMEM_BW + n * ROW_STRIDE_B + ((lane & 8) ? 16 : 0);
    }

    float acc[8][4];
#pragma unroll
    for (int j = 0; j < 8; ++j)
#pragma unroll
        for (int i = 0; i < 4; ++i) acc[j][i] = 0.f;

#pragma unroll
    for (int kk = 0; kk < 18; ++kk) {
        uint32_t a0, a1, a2, a3;
        ldsm_x4(a0, a1, a2, a3, aAddr + kk * 32);
#pragma unroll
        for (int p = 0; p < 4; ++p) {
            uint32_t b0, b1, b2, b3;
            ldsm_x4(b0, b1, b2, b3, bAddr[p] + kk * 32);
            mma_bf16(acc[2 * p], a0, a1, a2, a3, b0, b1);
            mma_bf16(acc[2 * p + 1], a0, a1, a2, a3, b2, b3);
        }
    }

    // ---- Phase 3: stage D to smem (warp-private rows), then coalesced epilogue.
    float2* sO = (float2*)(smem + SMEM_SO);
    {
        int r1 = warp * 16 + (lane >> 2);
        int cL = lane & 3;
#pragma unroll
        for (int j = 0; j < 8; ++j) {
            int c2 = j * 4 + cL;
            sO[r1 * 34 + c2] = make_float2(acc[j][0], acc[j][1]);
            sO[(r1 + 8) * 34 + c2] = make_float2(acc[j][2], acc[j][3]);
        }
    }
    __syncwarp();

    int c4 = lane & 15;
    int half = lane >> 4;
    float4 cb = *(const float4*)&g_c[c4 * 4];
#pragma unroll
    for (int rr = 0; rr < 8; ++rr) {
        int le = warp * 16 + rr * 2 + half;
        long ge = base + le;
        if (ge < E) {
            float4 v = *(const float4*)((char*)sO + le * SO_ROW_B + c4 * 16);
            int s = src[ge];
            int d = dst[ge];
            float4 pa = *(const float4*)&g_Pa[(long)s * 64 + c4 * 4];
            float4 pc = *(const float4*)&g_Pc[(long)d * 64 + c4 * 4];
            float4 o;
            o.x = fmaxf(v.x + pa.x + pc.x + cb.x, 0.f);
            o.y = fmaxf(v.y + pa.y + pc.y + cb.y, 0.f);
            o.z = fmaxf(v.z + pa.z + pc.z + cb.z, 0.f);
            o.w = fmaxf(v.w + pa.w + pc.w + cb.w, 0.f);
            *(float4*)&out[ge * 64 + c4 * 4] = o;
        }
    }
}

// ---------------------------------------------------------------------------
extern "C" void kernel_launch(void* const* d_in, const int* in_sizes, int n_in,
                              void* d_out, int out_size) {
    const float* h   = (const float*)d_in[0];
    const float* e_h = (const float*)d_in[1];
    const float* ext = (const float*)d_in[2];
    const float* W1  = (const float*)d_in[3];
    const float* b1  = (const float*)d_in[4];
    const float* W2  = (const float*)d_in[5];
    const float* b2  = (const float*)d_in[6];
    const int* src   = (const int*)d_in[7];
    const int* dst   = (const int*)d_in[8];
    float* out = (float*)d_out;

    int E = in_sizes[7];
    int N = in_sizes[0] / NHID;
    int NT = (E + TILE_E - 1) / TILE_E;

    static int attr_done = 0;
    if (!attr_done) {
        cudaFuncSetAttribute(edge_kernel, cudaFuncAttributeMaxDynamicSharedMemorySize,
                             SMEM_TOTAL);
        attr_done = 1;
    }

    compose_kernel<<<(12352 + 255) / 256, 256>>>(W1, b1, W2, b2);
    bprep_kernel<<<(64 * ROW_STRIDE_BF16 + 255) / 256, 256>>>(W2);
    nodeproj_kernel<<<(N + 7) / 8, 256>>>(h, N);
    edge_kernel<<<NT, 256, SMEM_TOTAL>>>(e_h, ext, src, dst, out, E);
}

// round 14
// speedup vs baseline: 1.6892x; 1.6892x over previous
#include <cuda_runtime.h>
#include <cstdint>

#define NHID 64
#define EXTD 32
#define MAXN 50000
#define TILE_E 128

// A' = [ahi | alo], K=192. Row stride 200 bf16 = 400 B (=> +4 banks/row, ldmatrix conflict-free)
#define ROW_STRIDE_BF16 200
#define ROW_STRIDE_B 400
#define A_BYTES (128 * ROW_STRIDE_B)        // 51200
#define B_BYTES (64 * ROW_STRIDE_B)         // 25600
#define SMEM_A 0
#define SMEM_BW (A_BYTES)
#define SMEM_TOTAL (A_BYTES + B_BYTES)      // 76800 -> 2 CTAs/SM

// Device scratch
__device__ __align__(16) float g_M[192 * 64];
__device__ __align__(16) float g_c[64];
__device__ __align__(16) float g_Pa[MAXN * 64];
__device__ __align__(16) float g_Pc[MAXN * 64];
__device__ __align__(16) unsigned short g_Bf[64 * ROW_STRIDE_BF16];  // B' bf16 [n][k']

// ---------------- helpers ----------------
__device__ __forceinline__ uint32_t smem_u32(const void* p) {
    uint32_t a;
    asm("{ .reg .u64 t; cvta.to.shared.u64 t, %1; cvt.u32.u64 %0, t; }" : "=r"(a) : "l"(p));
    return a;
}
__device__ __forceinline__ uint32_t cvt_bf16x2(float hi, float lo) {
    uint32_t d;
    asm("cvt.rn.satfinite.bf16x2.f32 %0, %1, %2;" : "=r"(d) : "f"(hi), "f"(lo));
    return d;
}
__device__ __forceinline__ void ldsm_x4(uint32_t& r0, uint32_t& r1, uint32_t& r2, uint32_t& r3,
                                        uint32_t addr) {
    asm volatile("ldmatrix.sync.aligned.m8n8.x4.shared.b16 {%0,%1,%2,%3}, [%4];"
                 : "=r"(r0), "=r"(r1), "=r"(r2), "=r"(r3) : "r"(addr));
}
__device__ __forceinline__ void mma_bf16(float* d, uint32_t a0, uint32_t a1, uint32_t a2,
                                         uint32_t a3, uint32_t b0, uint32_t b1) {
    asm volatile("mma.sync.aligned.m16n8k16.row.col.f32.bf16.bf16.f32 "
                 "{%0,%1,%2,%3}, {%4,%5,%6,%7}, {%8,%9}, {%0,%1,%2,%3};"
                 : "+f"(d[0]), "+f"(d[1]), "+f"(d[2]), "+f"(d[3])
                 : "r"(a0), "r"(a1), "r"(a2), "r"(a3), "r"(b0), "r"(b1));
}

// ---------------------------------------------------------------------------
// Kernel 0: compose M = W1 @ W2a (192x64), c = b1 @ W2a + b2.
// ---------------------------------------------------------------------------
__global__ __launch_bounds__(256) void compose_kernel(const float* __restrict__ W1,
                                                      const float* __restrict__ b1,
                                                      const float* __restrict__ W2,
                                                      const float* __restrict__ b2) {
    int idx = blockIdx.x * blockDim.x + threadIdx.x;
    if (idx < 12288) {
        int r = idx >> 6, j = idx & 63;
        float s = 0.f;
#pragma unroll 16
        for (int k = 0; k < 64; ++k) s += W1[r * 64 + k] * W2[k * 64 + j];
        g_M[idx] = s;
    } else if (idx < 12352) {
        int j = idx - 12288;
        float s = b2[j];
#pragma unroll 16
        for (int k = 0; k < 64; ++k) s += b1[k] * W2[k * 64 + j];
        g_c[j] = s;
    }
}

// ---------------------------------------------------------------------------
// Kernel 0b: build bf16 B' [64][200]: k'=[0,96) bhi, [96,192) blo, pad 0.
// B[k][n] = k<64 ? g_M[(64+k)*64+n] : W2[k*64+n].
// ---------------------------------------------------------------------------
__global__ __launch_bounds__(256) void bprep_kernel(const float* __restrict__ W2) {
    int idx = blockIdx.x * blockDim.x + threadIdx.x;
    if (idx >= 64 * ROW_STRIDE_BF16) return;
    int n = idx / ROW_STRIDE_BF16;
    int kp = idx - n * ROW_STRIDE_BF16;
    unsigned short val = 0;
    if (kp < 192) {
        int k = (kp < 96) ? kp : (kp - 96);
        float b = (k < 64) ? g_M[(64 + k) * 64 + n] : W2[k * 64 + n];
        unsigned short hi = (unsigned short)(cvt_bf16x2(0.f, b) & 0xffffu);
        if (kp < 96) {
            val = hi;
        } else {
            float hf = __uint_as_float(((uint32_t)hi) << 16);
            val = (unsigned short)(cvt_bf16x2(0.f, b - hf) & 0xffffu);
        }
    }
    g_Bf[idx] = val;
}

// ---------------------------------------------------------------------------
// Kernel 1: node projections Pa = h @ Ma, Pc = h @ Mc. Warp per node.
// ---------------------------------------------------------------------------
__global__ __launch_bounds__(256) void nodeproj_kernel(const float* __restrict__ h,
                                                       int nNodes) {
    __shared__ float sMa[64 * 64];
    __shared__ float sMc[64 * 64];
    int tid = threadIdx.x;
    for (int i = tid; i < 64 * 64; i += blockDim.x) {
        sMa[i] = g_M[i];
        sMc[i] = g_M[128 * 64 + i];
    }
    __syncthreads();

    int warp = tid >> 5, lane = tid & 31;
    int n = blockIdx.x * 8 + warp;
    if (n >= nNodes || n >= MAXN) return;

    float h0 = h[n * 64 + lane];
    float h1 = h[n * 64 + 32 + lane];
    float a0 = 0.f, a1 = 0.f, c0 = 0.f, c1 = 0.f;
#pragma unroll
    for (int k = 0; k < 64; ++k) {
        float hk = __shfl_sync(0xffffffffu, (k < 32) ? h0 : h1, k & 31);
        a0 += hk * sMa[k * 64 + lane];
        a1 += hk * sMa[k * 64 + 32 + lane];
        c0 += hk * sMc[k * 64 + lane];
        c1 += hk * sMc[k * 64 + 32 + lane];
    }
    g_Pa[n * 64 + lane] = a0;
    g_Pa[n * 64 + 32 + lane] = a1;
    g_Pc[n * 64 + lane] = c0;
    g_Pc[n * 64 + 32 + lane] = c1;
}

// ---------------------------------------------------------------------------
// Kernel 2: edge GEMM via bf16 mma.sync. One 128-edge tile per block.
// D = ahi@(bhi) + ahi@(blo) + alo@(bhi); ahi/bhi fragments reused in registers.
// ---------------------------------------------------------------------------
__global__ __launch_bounds__(256, 2) void edge_kernel(const float* __restrict__ e_h,
                                                      const float* __restrict__ ext,
                                                      const int* __restrict__ src,
                                                      const int* __restrict__ dst,
                                                      float* __restrict__ out,
                                                      int E) {
    extern __shared__ __align__(16) char smem[];
    char* sA = smem + SMEM_A;
    char* sB = smem + SMEM_BW;
    uint32_t sb = smem_u32(smem);

    int tid = threadIdx.x;
    int warp = tid >> 5;
    int lane = tid & 31;
    long base = (long)blockIdx.x * TILE_E;

    // ---- Phase 1: convert A tile (fp32 -> 2-block bf16 split [ahi|alo]) + copy B'
#pragma unroll
    for (int it = 0; it < 8; ++it) {          // e_h: 128 x 64 = 2048 float4
        int p = tid + it * 256;
        int e = p >> 4;
        int k0 = (p & 15) << 2;
        long ge = base + e;
        float4 x = make_float4(0.f, 0.f, 0.f, 0.f);
        if (ge < E) x = *(const float4*)&e_h[ge * 64 + k0];
        uint32_t hi01 = cvt_bf16x2(x.y, x.x);
        uint32_t hi23 = cvt_bf16x2(x.w, x.z);
        float r0 = x.x - __uint_as_float(hi01 << 16);
        float r1 = x.y - __uint_as_float(hi01 & 0xffff0000u);
        float r2 = x.z - __uint_as_float(hi23 << 16);
        float r3 = x.w - __uint_as_float(hi23 & 0xffff0000u);
        uint32_t lo01 = cvt_bf16x2(r1, r0);
        uint32_t lo23 = cvt_bf16x2(r3, r2);
        char* row = sA + e * ROW_STRIDE_B;
        *(uint2*)(row + k0 * 2) = make_uint2(hi01, hi23);
        *(uint2*)(row + (k0 + 96) * 2) = make_uint2(lo01, lo23);
    }
#pragma unroll
    for (int it = 0; it < 4; ++it) {          // ext: 128 x 32 = 1024 float4
        int p = tid + it * 256;
        int e = p >> 3;
        int k0 = 64 + ((p & 7) << 2);
        long ge = base + e;
        float4 x = make_float4(0.f, 0.f, 0.f, 0.f);
        if (ge < E) x = *(const float4*)&ext[ge * 32 + (k0 - 64)];
        uint32_t hi01 = cvt_bf16x2(x.y, x.x);
        uint32_t hi23 = cvt_bf16x2(x.w, x.z);
        float r0 = x.x - __uint_as_float(hi01 << 16);
        float r1 = x.y - __uint_as_float(hi01 & 0xffff0000u);
        float r2 = x.z - __uint_as_float(hi23 << 16);
        float r3 = x.w - __uint_as_float(hi23 & 0xffff0000u);
        uint32_t lo01 = cvt_bf16x2(r1, r0);
        uint32_t lo23 = cvt_bf16x2(r3, r2);
        char* row = sA + e * ROW_STRIDE_B;
        *(uint2*)(row + k0 * 2) = make_uint2(hi01, hi23);
        *(uint2*)(row + (k0 + 96) * 2) = make_uint2(lo01, lo23);
    }
    // B' copy: 25600 B = 1600 float4
#pragma unroll
    for (int it = 0; it < 7; ++it) {
        int p = tid + it * 256;
        if (p < 1600) *(float4*)(sB + p * 16) = *(const float4*)((const char*)g_Bf + p * 16);
    }
    __syncthreads();

    // ---- Phase 2: HMMA mainloop. Warp: 16 edges x 64 cols; 6 k16-steps x 3 terms.
    uint32_t aAddrHi = sb + SMEM_A + (warp * 16 + (lane & 15)) * ROW_STRIDE_B
                       + ((lane & 16) ? 16 : 0);
    uint32_t aAddrLo = aAddrHi + 192;          // +96 bf16
    uint32_t bAddrHi[4];
#pragma unroll
    for (int p = 0; p < 4; ++p) {
        int n = p * 16 + (lane & 7) + ((lane & 16) ? 8 : 0);
        bAddrHi[p] = sb + SMEM_BW + n * ROW_STRIDE_B + ((lane & 8) ? 16 : 0);
    }

    float acc[8][4];
#pragma unroll
    for (int j = 0; j < 8; ++j)
#pragma unroll
        for (int i = 0; i < 4; ++i) acc[j][i] = 0.f;

#pragma unroll
    for (int kk = 0; kk < 6; ++kk) {
        uint32_t ah0, ah1, ah2, ah3, al0, al1, al2, al3;
        ldsm_x4(ah0, ah1, ah2, ah3, aAddrHi + kk * 32);
        ldsm_x4(al0, al1, al2, al3, aAddrLo + kk * 32);
#pragma unroll
        for (int p = 0; p < 4; ++p) {
            uint32_t bh0, bh1, bh2, bh3, bl0, bl1, bl2, bl3;
            ldsm_x4(bh0, bh1, bh2, bh3, bAddrHi[p] + kk * 32);
            mma_bf16(acc[2 * p],     ah0, ah1, ah2, ah3, bh0, bh1);
            mma_bf16(acc[2 * p + 1], ah0, ah1, ah2, ah3, bh2, bh3);
            mma_bf16(acc[2 * p],     al0, al1, al2, al3, bh0, bh1);
            mma_bf16(acc[2 * p + 1], al0, al1, al2, al3, bh2, bh3);
            ldsm_x4(bl0, bl1, bl2, bl3, bAddrHi[p] + 192 + kk * 32);
            mma_bf16(acc[2 * p],     ah0, ah1, ah2, ah3, bl0, bl1);
            mma_bf16(acc[2 * p + 1], ah0, ah1, ah2, ah3, bl2, bl3);
        }
    }

    // ---- Phase 3: stage D into this warp's own (dead) A rows, then epilogue.
    // Warp-private region: rows warp*16 .. warp*16+15 of sA. __syncwarp only.
    {
        int r1 = warp * 16 + (lane >> 2);
        int cL = lane & 3;
#pragma unroll
        for (int j = 0; j < 8; ++j) {
            int c2 = j * 4 + cL;
            *(float2*)(sA + r1 * ROW_STRIDE_B + c2 * 8) = make_float2(acc[j][0], acc[j][1]);
            *(float2*)(sA + (r1 + 8) * ROW_STRIDE_B + c2 * 8) = make_float2(acc[j][2], acc[j][3]);
        }
    }
    __syncwarp();

    int c4 = lane & 15;
    int half = lane >> 4;
    float4 cb = *(const float4*)&g_c[c4 * 4];
#pragma unroll
    for (int rr = 0; rr < 8; ++rr) {
        int le = warp * 16 + rr * 2 + half;
        long ge = base + le;
        if (ge < E) {
            float4 v = *(const float4*)(sA + le * ROW_STRIDE_B + c4 * 16);
            int s = src[ge];
            int d = dst[ge];
            float4 pa = *(const float4*)&g_Pa[(long)s * 64 + c4 * 4];
            float4 pc = *(const float4*)&g_Pc[(long)d * 64 + c4 * 4];
            float4 o;
            o.x = fmaxf(v.x + pa.x + pc.x + cb.x, 0.f);
            o.y = fmaxf(v.y + pa.y + pc.y + cb.y, 0.f);
            o.z = fmaxf(v.z + pa.z + pc.z + cb.z, 0.f);
            o.w = fmaxf(v.w + pa.w + pc.w + cb.w, 0.f);
            *(float4*)&out[ge * 64 + c4 * 4] = o;
        }
    }
}

// ---------------------------------------------------------------------------
extern "C" void kernel_launch(void* const* d_in, const int* in_sizes, int n_in,
                              void* d_out, int out_size) {
    const float* h   = (const float*)d_in[0];
    const float* e_h = (const float*)d_in[1];
    const float* ext = (const float*)d_in[2];
    const float* W1  = (const float*)d_in[3];
    const float* b1  = (const float*)d_in[4];
    const float* W2  = (const float*)d_in[5];
    const float* b2  = (const float*)d_in[6];
    const int* src   = (const int*)d_in[7];
    const int* dst   = (const int*)d_in[8];
    float* out = (float*)d_out;

    int E = in_sizes[7];
    int N = in_sizes[0] / NHID;
    int NT = (E + TILE_E - 1) / TILE_E;

    static int attr_done = 0;
    if (!attr_done) {
        cudaFuncSetAttribute(edge_kernel, cudaFuncAttributeMaxDynamicSharedMemorySize,
                             SMEM_TOTAL);
        attr_done = 1;
    }

    compose_kernel<<<(12352 + 255) / 256, 256>>>(W1, b1, W2, b2);
    bprep_kernel<<<(64 * ROW_STRIDE_BF16 + 255) / 256, 256>>>(W2);
    nodeproj_kernel<<<(N + 7) / 8, 256>>>(h, N);
    edge_kernel<<<NT, 256, SMEM_TOTAL>>>(e_h, ext, src, dst, out, E);
}